// round 16
// baseline (speedup 1.0000x reference)
#include <cuda_runtime.h>
#include <cuda_fp16.h>
#include <cstdint>

#define TT 2048
#define HH 4096
#define OO 4096
#define LL 32
#define RR 16
#define NB 33   /* 32 adapters + bucket 32 for idx == -1 */

// ---------------- device scratch (no cudaMalloc allowed) ----------------
__device__ __half g_xh[TT * HH];   // fp16 x, row-major [T][H]
__device__ __half g_wh[OO * HH];   // fp16 W, row-major [O][H]
__device__ int   g_cnt[NB];
__device__ int   g_off[NB];
__device__ int   g_tok[TT];
__device__ float g_shrunk[TT * RR];
__device__ int   g_prep_done;      // set by pre/prep, cleared by main
__device__ int   g_exp_done;       // incremented by expand blocks, cleared by pre/prep

// ---------------- helpers ----------------
__device__ __forceinline__ uint32_t sw128(uint32_t off) {
    return off ^ ((off >> 3) & 0x70);
}
__device__ __forceinline__ void ldsm_x4(uint32_t* r, uint32_t addr) {
    asm volatile("ldmatrix.sync.aligned.m8n8.x4.shared.b16 {%0,%1,%2,%3}, [%4];"
                 : "=r"(r[0]), "=r"(r[1]), "=r"(r[2]), "=r"(r[3]) : "r"(addr));
}
__device__ __forceinline__ void mma_f16(float* c, const uint32_t* a, uint32_t b0, uint32_t b1) {
    asm volatile(
        "mma.sync.aligned.m16n8k16.row.col.f32.f16.f16.f32 "
        "{%0,%1,%2,%3}, {%4,%5,%6,%7}, {%8,%9}, {%0,%1,%2,%3};"
        : "+f"(c[0]), "+f"(c[1]), "+f"(c[2]), "+f"(c[3])
        : "r"(a[0]), "r"(a[1]), "r"(a[2]), "r"(a[3]), "r"(b0), "r"(b1));
}
__device__ __forceinline__ void cp16(uint32_t dst, const void* src) {
    asm volatile("cp.async.cg.shared.global [%0], [%1], 16;" :: "r"(dst),
                 "l"((unsigned long long)__cvta_generic_to_global((void*)src)));
}
__device__ __forceinline__ uint32_t smem_u32(const void* p) {
    uint32_t a;
    asm("{ .reg .u64 t; cvta.to.shared.u64 t, %1; cvt.u32.u64 %0, t; }" : "=r"(a) : "l"(p));
    return a;
}

// ---------------- pre: prep + shrink + fp16 converts, one kernel ----------------
// bid 0: prep; bids 1..256: shrink; bids 257..: converts (4096 x-blocks, 8192 w-blocks)
#define XBLKS (TT * HH / 8 / 256)    /* 4096 */
#define WBLKS (OO * HH / 8 / 256)    /* 8192 */
#define PRE_GRID (1 + 256 + XBLKS + WBLKS)
#define SCH 512

__global__ void __launch_bounds__(256) pre_kernel(const float* __restrict__ x,
                                                  const float* __restrict__ w,
                                                  const float* __restrict__ lora_a,
                                                  const int* __restrict__ idx) {
    int bid = blockIdx.x;
    int tid = threadIdx.x;

    if (bid == 0) {
        // ---- prep: zero state, detect index width, group tokens into 33 buckets ----
        __shared__ int s_ok;
        __shared__ int s_cnt[NB];
        __shared__ int s_off[NB];
        for (int i = tid; i < TT * RR; i += 256) g_shrunk[i] = 0.0f;
        if (tid == 0) { s_ok = 1; g_exp_done = 0; }
        if (tid < NB) s_cnt[tid] = 0;
        __syncthreads();
        // int64 detection: as int32 pairs (lo,hi), hi must sign-extend an index in [-1, LL)
        for (int t = tid; t < 1024; t += 256) {
            int lo = idx[2 * t], hi = idx[2 * t + 1];
            int expect = (lo < 0) ? -1 : 0;
            if (hi != expect || lo < -1 || lo >= LL) atomicExch(&s_ok, 0);
        }
        __syncthreads();
        int is64 = s_ok;
        for (int t = tid; t < TT; t += 256) {
            int l = is64 ? idx[2 * t] : idx[t];
            int b = (l < 0) ? 32 : l;
            atomicAdd(&s_cnt[b], 1);
        }
        __syncthreads();
        if (tid == 0) {
            int a = 0;
            for (int b = 0; b < NB; b++) { s_off[b] = a; a += s_cnt[b]; }
        }
        __syncthreads();
        if (tid < NB) { g_off[tid] = s_off[tid]; g_cnt[tid] = s_cnt[tid]; }
        if (tid < NB) s_cnt[tid] = 0;
        __syncthreads();
        for (int t = tid; t < TT; t += 256) {
            int l = is64 ? idx[2 * t] : idx[t];
            int b = (l < 0) ? 32 : l;
            int p = atomicAdd(&s_cnt[b], 1);
            g_tok[s_off[b] + p] = t;
        }
        __syncthreads();
        if (tid == 0) {
            __threadfence();
            atomicExch(&g_prep_done, 1);
        }
        return;
    }

    if (bid <= 256) {
        // ---- shrink: S[t,r] += x[t,chunk] . A[l,r,chunk]  (adapters 0..31) ----
        // __align__(16) is load-bearing: accessed via float4, and prep's shared
        // vars would otherwise push this to a non-16B static smem offset.
        __shared__ __align__(16) float As[RR * SCH];   // 32 KB static
        int e  = bid - 1;
        int l  = e & 31;
        int ch = e >> 5;
        int c0 = ch * SCH;
        const float* Ag = lora_a + (size_t)l * RR * HH + c0;
        for (int i = tid; i < RR * SCH / 4; i += 256) {
            int r = i >> 7;
            int c = (i & 127) * 4;
            *reinterpret_cast<float4*>(As + r * SCH + c) =
                *reinterpret_cast<const float4*>(Ag + (size_t)r * HH + c);
        }
        // wait for prep (all of wave 1 is co-resident; prep has no dependencies)
        if (tid == 0) {
            while (atomicAdd(&g_prep_done, 0) == 0) { __nanosleep(64); }
        }
        __syncthreads();
        int cnt = g_cnt[l], off = g_off[l];
        int wrp = tid >> 5, lane = tid & 31;
        for (int it = wrp; it < cnt; it += 8) {
            int t = g_tok[off + it];
            const float* xr = x + (size_t)t * HH + c0;
            float xv[16];
#pragma unroll
            for (int j = 0; j < 16; j++) xv[j] = xr[lane + 32 * j];
            float mine = 0.0f;
#pragma unroll
            for (int r = 0; r < RR; r++) {
                float a = 0.0f;
                const float* Ar = As + r * SCH;
#pragma unroll
                for (int j = 0; j < 16; j++) a += xv[j] * Ar[lane + 32 * j];
#pragma unroll
                for (int o = 16; o; o >>= 1) a += __shfl_xor_sync(0xFFFFFFFFu, a, o);
                if (lane == r) mine = a;
            }
            if (lane < RR) atomicAdd(&g_shrunk[t * RR + lane], mine);
        }
        return;
    }

    // ---- fp16 converts ----
    int cb = bid - 257;
    const float* src = (cb < XBLKS) ? x : w;
    __half* dst = (cb < XBLKS) ? g_xh : g_wh;
    size_t i = ((size_t)(cb < XBLKS ? cb : cb - XBLKS) * 256 + tid) * 8;
    float4 v0 = *reinterpret_cast<const float4*>(src + i);
    float4 v1 = *reinterpret_cast<const float4*>(src + i + 4);
    float f[8] = {v0.x, v0.y, v0.z, v0.w, v1.x, v1.y, v1.z, v1.w};
    __align__(16) __half h[8];
#pragma unroll
    for (int q = 0; q < 8; q++) h[q] = __float2half_rn(f[q]);
    *reinterpret_cast<uint4*>(dst + i) = *reinterpret_cast<uint4*>(h);
}

// ---------------- main: expand-write blocks + GEMM (RMW epilogue) ----------------
// bids 0..263: expand-write  out[t, chunk] = bias (+ lora);  bucket 32 = bias only
// bids 264..775: GEMM tile; epilogue spins on g_exp_done then out += acc
#define EXPBLKS (NB * 8)              /* 264 */
#define BK       64
#define NITER    (HH / BK)            /* 64 */
#define TILE16K  16384
#define STAGE_B  32768
#define NSTAGE   3
#define GEMM_SMEM (NSTAGE * STAGE_B)  /* 98304 */

__global__ void __launch_bounds__(256, 2) main_kernel(const float* __restrict__ lora_b,
                                                      const float* __restrict__ bias,
                                                      float* __restrict__ out) {
    extern __shared__ char smem[];
    int bid = blockIdx.x;
    int tid = threadIdx.x;

    if (bid == EXPBLKS) {
        // reset pre's flag for the next replay (pre kernel is fully done by now)
        if (tid == 0) g_prep_done = 0;
    }

    if (bid < EXPBLKS) {
        // ---- expand-write: out[t, o0:o0+512] = bias + sum_r S[t,r]*B[l,o,r] ----
        int l  = bid >> 3;         // 0..32
        int oc = bid & 7;
        int o0 = oc * 512;
        int cnt = g_cnt[l], off = g_off[l];
        if (l == 32) {
            // bias-only tokens
            for (int it = 0; it < cnt; it++) {
                int t = g_tok[off + it];
#pragma unroll
                for (int u = 0; u < 2; u++) {
                    int o = tid + u * 256;
                    out[(size_t)t * OO + o0 + o] = bias[o0 + o];
                }
            }
        } else {
            float* Bs = reinterpret_cast<float*>(smem);   // 512*17 floats in dynamic smem
            const float* Bg = lora_b + ((size_t)l * OO + o0) * RR;
            for (int i = tid; i < 512 * RR; i += 256) {
                int o = i >> 4, r = i & 15;
                Bs[o * 17 + r] = Bg[i];
            }
            __syncthreads();
            for (int it = 0; it < cnt; it++) {
                int t = g_tok[off + it];
                const float* sv = g_shrunk + t * RR;
                float s[RR];
#pragma unroll
                for (int r = 0; r < RR; r++) s[r] = __ldg(sv + r);
#pragma unroll
                for (int u = 0; u < 2; u++) {
                    int o = tid + u * 256;
                    float acc = bias[o0 + o];
#pragma unroll
                    for (int r = 0; r < RR; r++) acc += Bs[o * 17 + r] * s[r];
                    out[(size_t)t * OO + o0 + o] = acc;
                }
            }
        }
        __syncthreads();
        if (tid == 0) {
            __threadfence();
            atomicAdd(&g_exp_done, 1);
        }
        return;
    }

    // ---- GEMM tile ----
    uint32_t sb = smem_u32(smem);
    int g = bid - EXPBLKS;
    int ntile = g & 31;
    int mtile = g >> 5;
    int lane = tid & 31, wid = tid >> 5;
    int wm = wid & 1, wn = wid >> 1;          // warp grid 2 (M) x 4 (N)

    float acc[4][4][4];
#pragma unroll
    for (int i = 0; i < 4; i++)
#pragma unroll
        for (int j = 0; j < 4; j++)
#pragma unroll
            for (int q = 0; q < 4; q++) acc[i][j][q] = 0.0f;

    auto stage_load = [&](uint32_t sbase, int iter) {
        int koff = iter * BK;
#pragma unroll
        for (int q = 0; q < 8; q++) {
            int j = q * 256 + tid;          // 0..2047
            int tile = j >> 10;             // 0:A 1:B
            int u = j & 1023;
            int row = u >> 3, seg = u & 7;
            const __half* src = tile
                ? g_wh + (size_t)(ntile * 128 + row) * HH + koff + seg * 8
                : g_xh + (size_t)(mtile * 128 + row) * HH + koff + seg * 8;
            cp16(sbase + tile * TILE16K + sw128(row * 128 + seg * 16), src);
        }
    };

    // prologue: 2 stages in flight
#pragma unroll
    for (int s = 0; s < NSTAGE - 1; s++) {
        stage_load(sb + s * STAGE_B, s);
        asm volatile("cp.async.commit_group;" ::: "memory");
    }

    int arow = (lane & 15);
    int achk = (lane >> 4) * 16;

    int cur = 0, wrt = NSTAGE - 1;
    for (int it = 0; it < NITER; it++) {
        asm volatile("cp.async.wait_group 1;" ::: "memory");
        __syncthreads();
        if (it + NSTAGE - 1 < NITER) {
            stage_load(sb + wrt * STAGE_B, it + NSTAGE - 1);
        }
        asm volatile("cp.async.commit_group;" ::: "memory");

        uint32_t Ab = sb + cur * STAGE_B;
        uint32_t Bb = Ab + TILE16K;
#pragma unroll
        for (int ks = 0; ks < 4; ks++) {
            uint32_t a[4][4];
#pragma unroll
            for (int i = 0; i < 4; i++) {
                int row = wm * 64 + i * 16 + arow;
                uint32_t off = sw128(row * 128 + ks * 32 + achk);
                ldsm_x4(a[i], Ab + off);
            }
            uint32_t b[2][4];
#pragma unroll
            for (int jj = 0; jj < 2; jj++) {
                int row = wn * 32 + jj * 16 + arow;
                uint32_t off = sw128(row * 128 + ks * 32 + achk);
                ldsm_x4(b[jj], Bb + off);   // smem holds [n][k]: pairs are k-pairs
            }
#pragma unroll
            for (int i = 0; i < 4; i++)
#pragma unroll
                for (int j = 0; j < 4; j++) {
                    int jj = j >> 1, p = j & 1;
                    mma_f16(acc[i][j], a[i], b[jj][p], b[jj][p + 2]);
                }
        }
        cur = (cur + 1 < NSTAGE) ? cur + 1 : 0;
        wrt = (wrt + 1 < NSTAGE) ? wrt + 1 : 0;
    }

    // wait for all expand-write blocks (they run in wave 1, done long before this)
    if (tid == 0) {
        while (atomicAdd(&g_exp_done, 0) < EXPBLKS) { __nanosleep(64); }
    }
    __syncthreads();

    // epilogue: out += acc (bias + lora already in out)
#pragma unroll
    for (int i = 0; i < 4; i++) {
#pragma unroll
        for (int j = 0; j < 4; j++) {
            int m = mtile * 128 + wm * 64 + i * 16 + (lane >> 2);
            int n = ntile * 128 + wn * 32 + j * 8 + (lane & 3) * 2;
            float* p0 = out + (size_t)m * OO + n;
            float* p1 = out + (size_t)(m + 8) * OO + n;
            float2 c0 = *reinterpret_cast<float2*>(p0);
            float2 c1 = *reinterpret_cast<float2*>(p1);
            c0.x += acc[i][j][0];
            c0.y += acc[i][j][1];
            c1.x += acc[i][j][2];
            c1.y += acc[i][j][3];
            *reinterpret_cast<float2*>(p0) = c0;
            *reinterpret_cast<float2*>(p1) = c1;
        }
    }
}

// stub symbol
__global__ void ColumnParallelLinearWithLoRA_893353198245_kernel() {}

// ---------------- launch ----------------
extern "C" void kernel_launch(void* const* d_in, const int* in_sizes, int n_in,
                              void* d_out, int out_size) {
    const float* x    = (const float*)d_in[0];
    const float* w    = (const float*)d_in[1];
    const float* bias = (const float*)d_in[2];
    const float* la   = (const float*)d_in[3];
    const float* lb   = (const float*)d_in[4];
    const int*   idx  = (const int*)d_in[5];
    float* out = (float*)d_out;

    cudaFuncSetAttribute(main_kernel, cudaFuncAttributeMaxDynamicSharedMemorySize, GEMM_SMEM);

    pre_kernel<<<PRE_GRID, 256>>>(x, w, la, idx);
    main_kernel<<<EXPBLKS + 512, 256, GEMM_SMEM>>>(lb, bias, out);
}